// round 7
// baseline (speedup 1.0000x reference)
#include <cuda_runtime.h>
#include <math.h>
#include <stdint.h>

// ---------------------------------------------------------------------------
// GDER: out[b] = mean( Rx^2 + Ry^2 ) over valid 498x498 map.
// sum(Gy) is cancellation noise => Gy/sum(Gy) taps ~1e15 and Ry^2 dominates by
// >1e16 relative. Only the Gy path is computed, as a separable conv
// Gy = A(y)*B(x), 1/sum(Gy) folded into vertical taps. sum(Gy) replicated on
// host in numpy's exact f64 pairwise order (validated R1-R6, rel_err ~8.7e-8).
//
// R7: warp-autonomous, barrier-free, smem-free redesign.
// Packing (col p, col p+250): lo outputs = cols 0..249, hi outputs = cols
// 250..497; no window ever crosses the seam. Each warp owns streams
// p in [50*band, 50*band+64) (2 per lane) and produces outputs
// q in [50*band, 50*band+50). Horizontal windows come from register
// shuffles of the vertical results of lanes L..L+7. No __syncthreads,
// no shared memory in the main loop at all.
// ---------------------------------------------------------------------------

#define NB        64
#define W         512
#define OUTW      498
#define TILE_ROWS 30
#define TILES_Y   17        // 17*30 = 510 >= 498
#define BANDS     5         // 5 bands x 50 packed outputs = 250 = all 498 cols
#define PARTS     (TILES_Y * BANDS)   // 85 partials per batch

typedef unsigned long long u64;

struct Weights {
    float hw[8];   // horizontal symmetric taps: hw[0..6] pair weights, hw[7] center
    float vw[7];   // vertical antisymmetric taps (scaled by 1/sum(Gy))
};

__device__ double g_partials[NB * PARTS];
__device__ int    g_count[NB];   // zero-initialized; self-resetting

// ---- f32x2 packed helpers (sm_100+) ----
__device__ __forceinline__ u64 pack2(float lo, float hi) {
    u64 r; asm("mov.b64 %0, {%1, %2};" : "=l"(r) : "f"(lo), "f"(hi)); return r;
}
__device__ __forceinline__ void unpack2(u64 v, float& lo, float& hi) {
    asm("mov.b64 {%0, %1}, %2;" : "=f"(lo), "=f"(hi) : "l"(v));
}
__device__ __forceinline__ u64 fma2(u64 a, u64 b, u64 c) {
    u64 d; asm("fma.rn.f32x2 %0, %1, %2, %3;" : "=l"(d) : "l"(a), "l"(b), "l"(c)); return d;
}
__device__ __forceinline__ u64 add2(u64 a, u64 b) {
    u64 d; asm("add.rn.f32x2 %0, %1, %2;" : "=l"(d) : "l"(a), "l"(b)); return d;
}
__device__ __forceinline__ u64 neg2(u64 a) { return a ^ 0x8000000080000000ull; }
__device__ __forceinline__ u64 shfl64(u64 v, int src) {
    return __shfl_sync(0xFFFFFFFFu, (unsigned long long)v, src);
}

__global__ __launch_bounds__(64, 8) void gder_kernel(const float* __restrict__ x,
                                                     Weights wt,
                                                     float* __restrict__ out)
{
    const int lane = threadIdx.x & 31;
    const int gw   = blockIdx.x * 2 + (threadIdx.x >> 5);   // global warp id
    const int band = gw % BANDS;
    const int tmp  = gw / BANDS;
    const int tileY = tmp % TILES_Y;
    const int batch = tmp / TILES_Y;
    const int y0   = tileY * TILE_ROWS;
    const int S    = band * 50;                // band's packed output base
    const float* __restrict__ img = x + (size_t)batch * W * W;

    // packed weights
    u64 hw2[8], vp[7];
    #pragma unroll
    for (int j = 0; j < 8; ++j) hw2[j] = pack2(wt.hw[j], wt.hw[j]);
    #pragma unroll
    for (int k = 0; k < 7; ++k) vp[k] = pack2(wt.vw[k], wt.vw[k]);
    #define HW2(j) (hw2[(j) < 8 ? (j) : 14 - (j)])

    const int p0      = S + 2 * lane;          // streams p0, p0+1; lanes (col p, col p+250)
    const bool loadHi = (p0 <= 260);           // hi float2 (p0+250, p0+251) in bounds
    const bool oLane  = (lane <= 24);          // lanes producing outputs
    // hi-lane output validity: hi col = q + 250 <= 497  =>  q <= 247
    const u64 m0 = (p0     <= 247) ? ~0ull : 0x00000000FFFFFFFFull;
    const u64 m1 = (p0 + 1 <= 247) ? ~0ull : 0x00000000FFFFFFFFull;

    const float* __restrict__ pL = img + p0;
    const float* __restrict__ pH = img + p0 + 250;

    // register ring: 15 rows x 2 packed streams
    u64 h0[15], h1[15];
    #pragma unroll
    for (int i = 0; i < 14; ++i) {
        const float2 L = *reinterpret_cast<const float2*>(pL + (size_t)(y0 + i) * W);
        float2 Hv = make_float2(0.f, 0.f);
        if (loadHi) Hv = *reinterpret_cast<const float2*>(pH + (size_t)(y0 + i) * W);
        h0[i] = pack2(L.x, Hv.x);
        h1[i] = pack2(L.y, Hv.y);
    }

    // prefetch first compute row (y0+14 <= 509 always valid)
    float2 pfL = *reinterpret_cast<const float2*>(pL + (size_t)(y0 + 14) * W);
    float2 pfH = make_float2(0.f, 0.f);
    if (loadHi) pfH = *reinterpret_cast<const float2*>(pH + (size_t)(y0 + 14) * W);

    u64 facc = 0ull;

    for (int g = 0; g < 2; ++g) {
        #pragma unroll
        for (int p = 0; p < 15; ++p) {
            const int r = 15 * g + p;            // row within tile

            // consume prefetched row into ring slot (constant index per p)
            h0[(14 + p) % 15] = pack2(pfL.x, pfH.x);
            h1[(14 + p) % 15] = pack2(pfL.y, pfH.y);

            // prefetch next row, clamped (clamped data only feeds discarded
            // output rows >= 498)
            {
                int gr = y0 + 15 + r;
                gr = gr < (W - 1) ? gr : (W - 1);
                pfL = *reinterpret_cast<const float2*>(pL + (size_t)gr * W);
                if (loadHi)
                    pfH = *reinterpret_cast<const float2*>(pH + (size_t)gr * W);
            }

            // vertical (antisymmetric): s = A - B
            u64 a0 = 0ull, b0 = 0ull, a1 = 0ull, b1 = 0ull;
            #pragma unroll
            for (int k = 0; k < 7; ++k) {
                a0 = fma2(vp[k], h0[(p + k) % 15], a0);
                b0 = fma2(vp[k], h0[(p + 14 - k) % 15], b0);
                a1 = fma2(vp[k], h1[(p + k) % 15], a1);
                b1 = fma2(vp[k], h1[(p + 14 - k) % 15], b1);
            }
            const u64 s0 = add2(a0, neg2(b0));   // stream p0
            const u64 s1 = add2(a1, neg2(b1));   // stream p0+1

            // horizontal via warp shuffles (row valid check is warp-uniform)
            if (y0 + r < OUTW) {
                // outputs q0 = p0, q1 = p0+1; window v[q0 .. q0+15] comes
                // from s0/s1 of lanes L..L+7 (lanes > 24 produce garbage
                // that is never accumulated)
                u64 o0 = 0ull, o1 = 0ull;
                #pragma unroll
                for (int d = 0; d < 8; ++d) {
                    const u64 a = shfl64(s0, lane + d);   // w[2d]
                    const u64 b = shfl64(s1, lane + d);   // w[2d+1]
                    o0 = fma2(HW2(2 * d), a, o0);
                    if (d <= 6) o0 = fma2(HW2(2 * d + 1), b, o0);
                    if (d >= 1) o1 = fma2(HW2(2 * d - 1), a, o1);
                    o1 = fma2(HW2(2 * d), b, o1);
                }
                if (oLane) {
                    o0 &= m0;
                    o1 &= m1;
                    facc = fma2(o0, o0, facc);
                    facc = fma2(o1, o1, facc);
                }
            }
        }
    }

    // warp-level deterministic reduction in double
    float flo, fhi;
    unpack2(facc, flo, fhi);
    double dsum = (double)flo + (double)fhi;
    #pragma unroll
    for (int off = 16; off > 0; off >>= 1)
        dsum += __shfl_down_sync(0xFFFFFFFFu, dsum, off);

    if (lane == 0) {
        g_partials[batch * PARTS + tileY * BANDS + band] = dsum;
        __threadfence();
        const int old = atomicAdd(&g_count[batch], 1);
        if (old == PARTS - 1) {   // last warp for this batch: fixed-order sum
            __threadfence();
            double s = 0.0;
            #pragma unroll
            for (int i = 0; i < PARTS; ++i)
                s += __ldcg(&g_partials[batch * PARTS + i]);
            out[batch] = (float)(s * (1.0 / ((double)OUTW * (double)OUTW)));
            g_count[batch] = 0;   // reset for next graph replay
        }
    }
}

// ---------------------------------------------------------------------------
// Host side: replicate numpy float64 semantics exactly (validated R1-R6).
// ---------------------------------------------------------------------------

// numpy's pairwise_sum for contiguous float64 (PW_BLOCKSIZE = 128)
static double np_pairwise(const double* a, int n)
{
    if (n < 8) {
        double res = 0.0;
        for (int i = 0; i < n; ++i) res += a[i];
        return res;
    }
    else if (n <= 128) {
        double r[8];
        for (int j = 0; j < 8; ++j) r[j] = a[j];
        int i;
        for (i = 8; i < n - (n % 8); i += 8)
            for (int j = 0; j < 8; ++j) r[j] += a[i + j];
        double res = ((r[0] + r[1]) + (r[2] + r[3])) + ((r[4] + r[5]) + (r[6] + r[7]));
        for (; i < n; ++i) res += a[i];
        return res;
    }
    else {
        int n2 = n / 2;
        n2 -= n2 % 8;
        return np_pairwise(a, n2) + np_pairwise(a + n2, n - n2);
    }
}

extern "C" void kernel_launch(void* const* d_in, const int* in_sizes, int n_in,
                              void* d_out, int out_size)
{
    (void)in_sizes; (void)n_in; (void)out_size;
    const float* x  = (const float*)d_in[0];
    float*      out = (float*)d_out;

    const double sig     = 7.0 / 2.5;              // N=15//2=7; sig = N/2.5
    const double sig2    = pow(sig, 2.0);          // sig ** 2 (CPython float_pow -> libm pow)
    const double twosig2 = 2.0 * sig2;
    const double denomG  = (2.0 * M_PI) * sig;

    double Gy[225];
    for (int i = 0; i < 15; ++i) {
        const int yy = i - 7;
        for (int j = 0; j < 15; ++j) {
            const int xx = j - 7;
            const double G = exp((double)(-(xx * xx + yy * yy)) / twosig2) / denomG;
            Gy[i * 15 + j] = ((double)(-yy) * G) / sig2;
        }
    }
    const double s = np_pairwise(Gy, 225);         // np.sum(Gy), numpy pairwise order

    Weights wt;
    for (int j = 0; j < 8; ++j) {
        const int xx = j - 7;
        wt.hw[j] = (float)(exp((double)(-(xx * xx)) / twosig2) / denomG);
    }
    for (int k = 0; k < 7; ++k) {
        const int yy = k - 7;
        const double A = (((double)(-yy) * exp((double)(-(yy * yy)) / twosig2)) / sig2) / s;
        wt.vw[k] = (float)A;
    }

    // 5440 warps = 2720 blocks of 64 threads (2 independent warps each)
    const int total_warps  = NB * TILES_Y * BANDS;
    const int total_blocks = total_warps / 2;
    gder_kernel<<<total_blocks, 64>>>(x, wt, out);
}

// round 9
// speedup vs baseline: 1.2296x; 1.2296x over previous
#include <cuda_runtime.h>
#include <math.h>
#include <stdint.h>

// ---------------------------------------------------------------------------
// GDER: out[b] = mean( Rx^2 + Ry^2 ) over valid 498x498 map.
// sum(Gy) is cancellation noise => Gy/sum(Gy) taps ~1e15 and Ry^2 dominates by
// >1e16 relative. Only the Gy path is computed, as a separable conv
// Gy = A(y)*B(x), 1/sum(Gy) folded into vertical taps. sum(Gy) replicated on
// host in numpy's exact f64 pairwise order (validated R1-R7, rel_err ~8.7e-8).
//
// R9 = R8 (exchange-free: horizontal-first per-thread from own 20-float LDG
// window, vertical on private register ring; no smem/barriers/shuffles in the
// main loop) + fix: doVert now bounded by i <= TILE, so tiles no longer
// double-count the next tile's first 3 rows (R8's 4.8% rel_err = 24/498).
// ---------------------------------------------------------------------------

#define NB        64
#define W         512
#define OUTW      498
#define TILE      56
#define TILES_Y   9        // 9*56 = 504 >= 498

typedef unsigned long long u64;

struct Weights {
    float hw[8];   // horizontal symmetric taps: hw[0..6] pair weights, hw[7] center
    float vw[7];   // vertical antisymmetric taps (scaled by 1/sum(Gy))
};

__device__ double g_partials[NB * TILES_Y];
__device__ int    g_count[NB];   // zero-initialized; self-resetting

// ---- f32x2 packed helpers (sm_100+) ----
__device__ __forceinline__ u64 pack2(float lo, float hi) {
    u64 r; asm("mov.b64 %0, {%1, %2};" : "=l"(r) : "f"(lo), "f"(hi)); return r;
}
__device__ __forceinline__ void unpack2(u64 v, float& lo, float& hi) {
    asm("mov.b64 {%0, %1}, %2;" : "=f"(lo), "=f"(hi) : "l"(v));
}
__device__ __forceinline__ u64 fma2(u64 a, u64 b, u64 c) {
    u64 d; asm("fma.rn.f32x2 %0, %1, %2, %3;" : "=l"(d) : "l"(a), "l"(b), "l"(c)); return d;
}
__device__ __forceinline__ u64 add2(u64 a, u64 b) {
    u64 d; asm("add.rn.f32x2 %0, %1, %2;" : "=l"(d) : "l"(a), "l"(b)); return d;
}
__device__ __forceinline__ u64 neg2(u64 a) { return a ^ 0x8000000080000000ull; }

__global__ __launch_bounds__(128, 4) void gder_kernel(const float* __restrict__ x,
                                                      Weights wt,
                                                      float* __restrict__ out)
{
    const int t     = threadIdx.x;
    const int tileY = blockIdx.x;
    const int batch = blockIdx.y;
    const int y0    = tileY * TILE;
    const float* __restrict__ img = x + (size_t)batch * W * W;

    __shared__ double red[128];

    // packed weights: horizontal mirrored taps via constant index, vertical 7
    u64 hw2[8], vp[7];
    #pragma unroll
    for (int j = 0; j < 8; ++j) hw2[j] = pack2(wt.hw[j], wt.hw[j]);
    #pragma unroll
    for (int k = 0; k < 7; ++k) vp[k] = pack2(wt.vw[k], wt.vw[k]);
    #define HWM(j) (hw2[(j) < 8 ? (j) : 14 - (j)])

    const int c = 4 * t;   // this thread's 4 output columns c..c+3

    // clamped column offsets for the 5 float4 loads (cols c..c+19, clamp 508)
    int a0c = c      > 508 ? 508 : c;
    int a1c = c + 4  > 508 ? 508 : c + 4;
    int a2c = c + 8  > 508 ? 508 : c + 8;
    int a3c = c + 12 > 508 ? 508 : c + 12;
    int a4c = c + 16 > 508 ? 508 : c + 16;

    // output validity masks (packed pairs A=(c,c+1), B=(c+2,c+3))
    const u64 LO = 0x00000000FFFFFFFFull, HI = 0xFFFFFFFF00000000ull;
    const u64 mA = (c     <= 497 ? LO : 0ull) | (c + 1 <= 497 ? HI : 0ull);
    const u64 mB = (c + 2 <= 497 ? LO : 0ull) | (c + 3 <= 497 ? HI : 0ull);

    // horizontal of one input row from the 20-float window -> packed pair
    float in[20];
    #define LOAD_ROW(yIn) do {                                                   \
        const float* rp = img + (size_t)(yIn) * W;                               \
        *reinterpret_cast<float4*>(&in[0])  = *reinterpret_cast<const float4*>(rp + a0c); \
        *reinterpret_cast<float4*>(&in[4])  = *reinterpret_cast<const float4*>(rp + a1c); \
        *reinterpret_cast<float4*>(&in[8])  = *reinterpret_cast<const float4*>(rp + a2c); \
        *reinterpret_cast<float4*>(&in[12]) = *reinterpret_cast<const float4*>(rp + a3c); \
        *reinterpret_cast<float4*>(&in[16]) = *reinterpret_cast<const float4*>(rp + a4c); \
    } while (0)

    #define HORIZ(hA, hB) do {                                                   \
        hA = 0ull; hB = 0ull;                                                    \
        _Pragma("unroll")                                                        \
        for (int j = 0; j < 17; ++j) {                                           \
            const u64 u = pack2(in[j], in[j + 1]);                               \
            if (j <= 14) hA = fma2(HWM(j), u, hA);                               \
            if (j >= 2)  hB = fma2(HWM(j - 2), u, hB);                           \
        }                                                                        \
    } while (0)

    // register ring of horizontal results: 15 rows x 2 packed pairs
    u64 rA[15], rB[15];
    #pragma unroll
    for (int i = 0; i < 14; ++i) {
        LOAD_ROW(y0 + i);                 // y0+13 <= 461, always valid
        HORIZ(rA[i], rB[i]);
    }

    u64 facc = 0ull;

    // skewed loop: iteration i loads/filters input row y0+14+i (slot (14+i)%15)
    // and computes vertical output row y0+i-1 BEFORE the insert.
    // Valid verticals: i in [1, TILE] -> output rows y0 .. y0+TILE-1 only.
    for (int g = 0; g < 4; ++g) {
        #pragma unroll
        for (int p = 0; p < 15; ++p) {
            const int i = g * 15 + p;
            const bool doLoad = (i < TILE) && (y0 + i < OUTW);
            const bool doVert = (i >= 1) && (i <= TILE) && (y0 + i - 1 < OUTW);

            // (1) issue loads for input row y0+14+i (clamped; clamped rows
            //     only feed discarded outputs >= 498)
            if (doLoad) {
                int yIn = y0 + 14 + i;
                yIn = yIn < (W - 1) ? yIn : (W - 1);
                LOAD_ROW(yIn);
            }

            // (2) vertical for output row y0+i-1 (pure register work — covers
            //     the LDG latency). Ring holds rows y0+i-1 .. y0+i+13.
            if (doVert) {
                u64 aA = 0ull, bA = 0ull, aB = 0ull, bB = 0ull;
                #pragma unroll
                for (int k = 0; k < 7; ++k) {
                    aA = fma2(vp[k], rA[(p - 1 + k + 15) % 15], aA);
                    bA = fma2(vp[k], rA[(p + 13 - k + 15) % 15], bA);
                    aB = fma2(vp[k], rB[(p - 1 + k + 15) % 15], aB);
                    bB = fma2(vp[k], rB[(p + 13 - k + 15) % 15], bB);
                }
                u64 oA = add2(aA, neg2(bA));
                u64 oB = add2(aB, neg2(bB));
                oA &= mA;
                oB &= mB;
                facc = fma2(oA, oA, facc);
                facc = fma2(oB, oB, facc);
            }

            // (3) horizontal of the loaded row, insert into ring slot (14+i)%15
            if (doLoad) {
                HORIZ(rA[(14 + p) % 15], rB[(14 + p) % 15]);
            }
        }
    }

    // deterministic block reduction in double (single barrier region per block)
    {
        float flo, fhi;
        unpack2(facc, flo, fhi);
        red[t] = (double)flo + (double)fhi;
    }
    __syncthreads();
    #pragma unroll
    for (int s = 64; s > 0; s >>= 1) {
        if (t < s) red[t] += red[t + s];
        __syncthreads();
    }
    if (t == 0) {
        g_partials[batch * TILES_Y + tileY] = red[0];
        __threadfence();
        const int old = atomicAdd(&g_count[batch], 1);
        if (old == TILES_Y - 1) {   // last block for this batch: fixed-order sum
            __threadfence();
            double s = 0.0;
            #pragma unroll
            for (int i = 0; i < TILES_Y; ++i)
                s += __ldcg(&g_partials[batch * TILES_Y + i]);
            out[batch] = (float)(s * (1.0 / ((double)OUTW * (double)OUTW)));
            g_count[batch] = 0;     // reset for next graph replay
        }
    }
}

// ---------------------------------------------------------------------------
// Host side: replicate numpy float64 semantics exactly (validated R1-R7).
// ---------------------------------------------------------------------------

// numpy's pairwise_sum for contiguous float64 (PW_BLOCKSIZE = 128)
static double np_pairwise(const double* a, int n)
{
    if (n < 8) {
        double res = 0.0;
        for (int i = 0; i < n; ++i) res += a[i];
        return res;
    }
    else if (n <= 128) {
        double r[8];
        for (int j = 0; j < 8; ++j) r[j] = a[j];
        int i;
        for (i = 8; i < n - (n % 8); i += 8)
            for (int j = 0; j < 8; ++j) r[j] += a[i + j];
        double res = ((r[0] + r[1]) + (r[2] + r[3])) + ((r[4] + r[5]) + (r[6] + r[7]));
        for (; i < n; ++i) res += a[i];
        return res;
    }
    else {
        int n2 = n / 2;
        n2 -= n2 % 8;
        return np_pairwise(a, n2) + np_pairwise(a + n2, n - n2);
    }
}

extern "C" void kernel_launch(void* const* d_in, const int* in_sizes, int n_in,
                              void* d_out, int out_size)
{
    (void)in_sizes; (void)n_in; (void)out_size;
    const float* x  = (const float*)d_in[0];
    float*      out = (float*)d_out;

    const double sig     = 7.0 / 2.5;              // N=15//2=7; sig = N/2.5
    const double sig2    = pow(sig, 2.0);          // sig ** 2 (CPython float_pow -> libm pow)
    const double twosig2 = 2.0 * sig2;
    const double denomG  = (2.0 * M_PI) * sig;

    double Gy[225];
    for (int i = 0; i < 15; ++i) {
        const int yy = i - 7;
        for (int j = 0; j < 15; ++j) {
            const int xx = j - 7;
            const double G = exp((double)(-(xx * xx + yy * yy)) / twosig2) / denomG;
            Gy[i * 15 + j] = ((double)(-yy) * G) / sig2;
        }
    }
    const double s = np_pairwise(Gy, 225);         // np.sum(Gy), numpy pairwise order

    Weights wt;
    for (int j = 0; j < 8; ++j) {
        const int xx = j - 7;
        wt.hw[j] = (float)(exp((double)(-(xx * xx)) / twosig2) / denomG);
    }
    for (int k = 0; k < 7; ++k) {
        const int yy = k - 7;
        const double A = (((double)(-yy) * exp((double)(-(yy * yy)) / twosig2)) / sig2) / s;
        wt.vw[k] = (float)A;
    }

    dim3 grid(TILES_Y, NB);
    gder_kernel<<<grid, 128>>>(x, wt, out);
}

// round 10
// speedup vs baseline: 1.3241x; 1.0769x over previous
#include <cuda_runtime.h>
#include <math.h>
#include <stdint.h>

// ---------------------------------------------------------------------------
// GDER: out[b] = mean( Rx^2 + Ry^2 ) over valid 498x498 map.
// sum(Gy) is cancellation noise => Gy/sum(Gy) taps ~1e15 and Ry^2 dominates by
// >1e16 relative. Only the Gy path is computed, as a separable conv
// Gy = A(y)*B(x), 1/sum(Gy) folded into vertical taps. sum(Gy) replicated on
// host in numpy's exact f64 pairwise order (validated R1-R9, rel_err ~8.7e-8).
//
// R10 = R9 exchange-free architecture + instruction diet:
//  - one base pointer, immediate-offset LDG.128s, +W per row (no per-row IMADs)
//  - stale-data skip instead of row clamping (skipped rows feed only
//    discarded outputs)
//  - edge threads handled at init: t>=125 clamped base (outputs masked),
//    t==124 does 4 loads with in[16..19]=0 (feeds only masked outputs)
//  - masks applied only in the edge warp; split accumulator chains
// ---------------------------------------------------------------------------

#define NB        64
#define W         512
#define OUTW      498
#define TILE      56
#define TILES_Y   9        // 9*56 = 504 >= 498

typedef unsigned long long u64;

struct Weights {
    float hw[8];   // horizontal symmetric taps: hw[0..6] pair weights, hw[7] center
    float vw[7];   // vertical antisymmetric taps (scaled by 1/sum(Gy))
};

__device__ double g_partials[NB * TILES_Y];
__device__ int    g_count[NB];   // zero-initialized; self-resetting

// ---- f32x2 packed helpers (sm_100+) ----
__device__ __forceinline__ u64 pack2(float lo, float hi) {
    u64 r; asm("mov.b64 %0, {%1, %2};" : "=l"(r) : "f"(lo), "f"(hi)); return r;
}
__device__ __forceinline__ void unpack2(u64 v, float& lo, float& hi) {
    asm("mov.b64 {%0, %1}, %2;" : "=f"(lo), "=f"(hi) : "l"(v));
}
__device__ __forceinline__ u64 fma2(u64 a, u64 b, u64 c) {
    u64 d; asm("fma.rn.f32x2 %0, %1, %2, %3;" : "=l"(d) : "l"(a), "l"(b), "l"(c)); return d;
}
__device__ __forceinline__ u64 add2(u64 a, u64 b) {
    u64 d; asm("add.rn.f32x2 %0, %1, %2;" : "=l"(d) : "l"(a), "l"(b)); return d;
}
__device__ __forceinline__ u64 neg2(u64 a) { return a ^ 0x8000000080000000ull; }

__global__ __launch_bounds__(128, 4) void gder_kernel(const float* __restrict__ x,
                                                      Weights wt,
                                                      float* __restrict__ out)
{
    const int t     = threadIdx.x;
    const int tileY = blockIdx.x;
    const int batch = blockIdx.y;
    const int y0    = tileY * TILE;
    const float* __restrict__ img = x + (size_t)batch * W * W;

    __shared__ double red[128];

    // packed weights
    u64 hw2[8], vp[7];
    #pragma unroll
    for (int j = 0; j < 8; ++j) hw2[j] = pack2(wt.hw[j], wt.hw[j]);
    #pragma unroll
    for (int k = 0; k < 7; ++k) vp[k] = pack2(wt.vw[k], wt.vw[k]);
    #define HWM(j) (hw2[(j) < 8 ? (j) : 14 - (j)])

    const int c = 4 * t;   // this thread's 4 output columns c..c+3

    // Base column:
    //  t <= 123 (c <= 492): cb = c, 5 loads, window c..c+19 in-row.
    //  t == 124 (c == 496): cb = 496, 4 loads (cols 496..511); in[16..19]
    //    zeroed once — they feed only outputs 498,499 which are masked.
    //  t >= 125 (c >= 500): cb = 492 (in-bounds), outputs fully masked.
    const int  cb  = (c <= 496) ? c : 492;
    const bool do5 = (c != 496);

    // output validity masks (packed pairs A=(c,c+1), B=(c+2,c+3))
    const u64 LOm = 0x00000000FFFFFFFFull, HIm = 0xFFFFFFFF00000000ull;
    const u64 mA = (c     <= 497 ? LOm : 0ull) | (c + 1 <= 497 ? HIm : 0ull);
    const u64 mB = (c + 2 <= 497 ? LOm : 0ull) | (c + 3 <= 497 ? HIm : 0ull);

    // walking row pointer: immediate-offset LDG.128s, +W per row
    const float* p = img + (size_t)y0 * W + cb;

    float in[20];
    in[16] = 0.f; in[17] = 0.f; in[18] = 0.f; in[19] = 0.f;

    #define LOAD_ROW() do {                                                       \
        *reinterpret_cast<float4*>(&in[0])  = *reinterpret_cast<const float4*>(p);      \
        *reinterpret_cast<float4*>(&in[4])  = *reinterpret_cast<const float4*>(p + 4);  \
        *reinterpret_cast<float4*>(&in[8])  = *reinterpret_cast<const float4*>(p + 8);  \
        *reinterpret_cast<float4*>(&in[12]) = *reinterpret_cast<const float4*>(p + 12); \
        if (do5)                                                                  \
            *reinterpret_cast<float4*>(&in[16]) = *reinterpret_cast<const float4*>(p + 16); \
    } while (0)

    // horizontal with split accumulator chains (8+7 deep instead of 15)
    #define HORIZ(hA, hB) do {                                                   \
        u64 hA0 = 0ull, hA1 = 0ull, hB0 = 0ull, hB1 = 0ull;                      \
        _Pragma("unroll")                                                        \
        for (int j = 0; j < 17; ++j) {                                           \
            const u64 u = pack2(in[j], in[j + 1]);                               \
            if (j <= 7)             hA0 = fma2(HWM(j), u, hA0);                  \
            else if (j <= 14)       hA1 = fma2(HWM(j), u, hA1);                  \
            if (j >= 2 && j <= 9)   hB0 = fma2(HWM(j - 2), u, hB0);              \
            else if (j >= 10)       hB1 = fma2(HWM(j - 2), u, hB1);              \
        }                                                                        \
        hA = add2(hA0, hA1);                                                     \
        hB = add2(hB0, hB1);                                                     \
    } while (0)

    // register ring of horizontal results: 15 rows x 2 packed pairs
    u64 rA[15], rB[15];
    #pragma unroll
    for (int i = 0; i < 14; ++i) {
        LOAD_ROW();                        // rows y0..y0+13 <= 461, always valid
        HORIZ(rA[i], rB[i]);
        p += W;
    }

    u64 fA = 0ull, fB = 0ull;

    // skewed loop: iteration i loads/filters input row y0+14+i and computes
    // vertical output row y0+i-1 (valid for i in [1, TILE]).
    for (int g = 0; g < 4; ++g) {
        #pragma unroll
        for (int q = 0; q < 15; ++q) {
            const int i = g * 15 + q;
            const bool doLoad = (i < TILE) && (y0 + 14 + i < W);
            const bool doVert = (i >= 1) && (i <= TILE) && (y0 + i - 1 < OUTW);

            // (1) loads for input row y0+14+i (skip => stale data, which only
            //     feeds discarded outputs >= 498)
            if (doLoad) LOAD_ROW();
            p += W;

            // (2) vertical for output row y0+i-1 (register-only; covers LDG)
            if (doVert) {
                u64 aA = 0ull, bA = 0ull, aB = 0ull, bB = 0ull;
                #pragma unroll
                for (int k = 0; k < 7; ++k) {
                    aA = fma2(vp[k], rA[(q - 1 + k + 15) % 15], aA);
                    bA = fma2(vp[k], rA[(q + 13 - k + 15) % 15], bA);
                    aB = fma2(vp[k], rB[(q - 1 + k + 15) % 15], aB);
                    bB = fma2(vp[k], rB[(q + 13 - k + 15) % 15], bB);
                }
                u64 oA = add2(aA, neg2(bA));
                u64 oB = add2(aB, neg2(bB));
                if (t >= 124) { oA &= mA; oB &= mB; }   // edge warp only
                fA = fma2(oA, oA, fA);
                fB = fma2(oB, oB, fB);
            }

            // (3) horizontal of the loaded row, insert into ring slot
            if (doLoad) {
                HORIZ(rA[(14 + q) % 15], rB[(14 + q) % 15]);
            }
        }
    }

    // deterministic block reduction in double
    {
        const u64 facc = add2(fA, fB);
        float flo, fhi;
        unpack2(facc, flo, fhi);
        red[t] = (double)flo + (double)fhi;
    }
    __syncthreads();
    #pragma unroll
    for (int s = 64; s > 0; s >>= 1) {
        if (t < s) red[t] += red[t + s];
        __syncthreads();
    }
    if (t == 0) {
        g_partials[batch * TILES_Y + tileY] = red[0];
        __threadfence();
        const int old = atomicAdd(&g_count[batch], 1);
        if (old == TILES_Y - 1) {   // last block for this batch: fixed-order sum
            __threadfence();
            double s = 0.0;
            #pragma unroll
            for (int i = 0; i < TILES_Y; ++i)
                s += __ldcg(&g_partials[batch * TILES_Y + i]);
            out[batch] = (float)(s * (1.0 / ((double)OUTW * (double)OUTW)));
            g_count[batch] = 0;     // reset for next graph replay
        }
    }
}

// ---------------------------------------------------------------------------
// Host side: replicate numpy float64 semantics exactly (validated R1-R9).
// ---------------------------------------------------------------------------

// numpy's pairwise_sum for contiguous float64 (PW_BLOCKSIZE = 128)
static double np_pairwise(const double* a, int n)
{
    if (n < 8) {
        double res = 0.0;
        for (int i = 0; i < n; ++i) res += a[i];
        return res;
    }
    else if (n <= 128) {
        double r[8];
        for (int j = 0; j < 8; ++j) r[j] = a[j];
        int i;
        for (i = 8; i < n - (n % 8); i += 8)
            for (int j = 0; j < 8; ++j) r[j] += a[i + j];
        double res = ((r[0] + r[1]) + (r[2] + r[3])) + ((r[4] + r[5]) + (r[6] + r[7]));
        for (; i < n; ++i) res += a[i];
        return res;
    }
    else {
        int n2 = n / 2;
        n2 -= n2 % 8;
        return np_pairwise(a, n2) + np_pairwise(a + n2, n - n2);
    }
}

extern "C" void kernel_launch(void* const* d_in, const int* in_sizes, int n_in,
                              void* d_out, int out_size)
{
    (void)in_sizes; (void)n_in; (void)out_size;
    const float* x  = (const float*)d_in[0];
    float*      out = (float*)d_out;

    const double sig     = 7.0 / 2.5;              // N=15//2=7; sig = N/2.5
    const double sig2    = pow(sig, 2.0);          // sig ** 2 (CPython float_pow -> libm pow)
    const double twosig2 = 2.0 * sig2;
    const double denomG  = (2.0 * M_PI) * sig;

    double Gy[225];
    for (int i = 0; i < 15; ++i) {
        const int yy = i - 7;
        for (int j = 0; j < 15; ++j) {
            const int xx = j - 7;
            const double G = exp((double)(-(xx * xx + yy * yy)) / twosig2) / denomG;
            Gy[i * 15 + j] = ((double)(-yy) * G) / sig2;
        }
    }
    const double s = np_pairwise(Gy, 225);         // np.sum(Gy), numpy pairwise order

    Weights wt;
    for (int j = 0; j < 8; ++j) {
        const int xx = j - 7;
        wt.hw[j] = (float)(exp((double)(-(xx * xx)) / twosig2) / denomG);
    }
    for (int k = 0; k < 7; ++k) {
        const int yy = k - 7;
        const double A = (((double)(-yy) * exp((double)(-(yy * yy)) / twosig2)) / sig2) / s;
        wt.vw[k] = (float)A;
    }

    dim3 grid(TILES_Y, NB);
    gder_kernel<<<grid, 128>>>(x, wt, out);
}

// round 11
// speedup vs baseline: 1.3427x; 1.0141x over previous
#include <cuda_runtime.h>
#include <math.h>
#include <stdint.h>

// ---------------------------------------------------------------------------
// GDER: out[b] = mean( Rx^2 + Ry^2 ) over valid 498x498 map.
// sum(Gy) is cancellation noise => Gy/sum(Gy) taps ~1e15 and Ry^2 dominates by
// >1e16 relative. Only the Gy path is computed, as a separable conv
// Gy = A(y)*B(x), 1/sum(Gy) folded into vertical taps. sum(Gy) replicated on
// host in numpy's exact f64 pairwise order (validated R1-R10, rel_err ~9e-8).
//
// R11 = R10 exchange-free architecture + aligned-pair HORIZ:
// LDG.128 destinations are 4 consecutive registers, so even-offset window
// pairs (f[2m], f[2m+1]) are ALREADY valid f32x2 operands (union view d[m])
// — zero MOVs. Only the 8 odd-offset pairs need pack2. Cuts ALU from ~47 to
// ~22 instr/row/warp.
// ---------------------------------------------------------------------------

#define NB        64
#define W         512
#define OUTW      498
#define TILE      56
#define TILES_Y   9        // 9*56 = 504 >= 498

typedef unsigned long long u64;

struct Weights {
    float hw[8];   // horizontal symmetric taps: hw[0..6] pair weights, hw[7] center
    float vw[7];   // vertical antisymmetric taps (scaled by 1/sum(Gy))
};

__device__ double g_partials[NB * TILES_Y];
__device__ int    g_count[NB];   // zero-initialized; self-resetting

// ---- f32x2 packed helpers (sm_100+) ----
__device__ __forceinline__ u64 pack2(float lo, float hi) {
    u64 r; asm("mov.b64 %0, {%1, %2};" : "=l"(r) : "f"(lo), "f"(hi)); return r;
}
__device__ __forceinline__ void unpack2(u64 v, float& lo, float& hi) {
    asm("mov.b64 {%0, %1}, %2;" : "=f"(lo), "=f"(hi) : "l"(v));
}
__device__ __forceinline__ u64 fma2(u64 a, u64 b, u64 c) {
    u64 d; asm("fma.rn.f32x2 %0, %1, %2, %3;" : "=l"(d) : "l"(a), "l"(b), "l"(c)); return d;
}
__device__ __forceinline__ u64 add2(u64 a, u64 b) {
    u64 d; asm("add.rn.f32x2 %0, %1, %2;" : "=l"(d) : "l"(a), "l"(b)); return d;
}
__device__ __forceinline__ u64 neg2(u64 a) { return a ^ 0x8000000080000000ull; }

__global__ __launch_bounds__(128, 4) void gder_kernel(const float* __restrict__ x,
                                                      Weights wt,
                                                      float* __restrict__ out)
{
    const int t     = threadIdx.x;
    const int tileY = blockIdx.x;
    const int batch = blockIdx.y;
    const int y0    = tileY * TILE;
    const float* __restrict__ img = x + (size_t)batch * W * W;

    __shared__ double red[128];

    // packed weights
    u64 hw2[8], vp[7];
    #pragma unroll
    for (int j = 0; j < 8; ++j) hw2[j] = pack2(wt.hw[j], wt.hw[j]);
    #pragma unroll
    for (int k = 0; k < 7; ++k) vp[k] = pack2(wt.vw[k], wt.vw[k]);
    #define HWM(j) (hw2[(j) < 8 ? (j) : 14 - (j)])

    const int c = 4 * t;   // this thread's 4 output columns c..c+3

    // Base column (edge handling at init only, see R10):
    //  t <= 123: cb = c, 5 loads.   t == 124: cb = 496, 4 loads, f[16..19]=0
    //  (feeds only masked outputs). t >= 125: cb = 492, outputs fully masked.
    const int  cb  = (c <= 496) ? c : 492;
    const bool do5 = (c != 496);

    // output validity masks (packed pairs A=(c,c+1), B=(c+2,c+3))
    const u64 LOm = 0x00000000FFFFFFFFull, HIm = 0xFFFFFFFF00000000ull;
    const u64 mA = (c     <= 497 ? LOm : 0ull) | (c + 1 <= 497 ? HIm : 0ull);
    const u64 mB = (c + 2 <= 497 ? LOm : 0ull) | (c + 3 <= 497 ? HIm : 0ull);

    // walking row pointer: immediate-offset LDG.128s, +W per row
    const float* p = img + (size_t)y0 * W + cb;

    // window buffer: union view so even pairs (f[2m], f[2m+1]) are the
    // register pairs written by the float4 loads (valid f32x2 operands)
    union InBuf { float f[20]; u64 d[10]; float4 v[5]; };
    InBuf in;
    in.f[16] = 0.f; in.f[17] = 0.f; in.f[18] = 0.f; in.f[19] = 0.f;

    #define LOAD_ROW() do {                                          \
        in.v[0] = *reinterpret_cast<const float4*>(p);               \
        in.v[1] = *reinterpret_cast<const float4*>(p + 4);           \
        in.v[2] = *reinterpret_cast<const float4*>(p + 8);           \
        in.v[3] = *reinterpret_cast<const float4*>(p + 12);          \
        if (do5) in.v[4] = *reinterpret_cast<const float4*>(p + 16); \
    } while (0)

    // window pair u_j = (f[j], f[j+1]):
    //   even j -> in.d[j/2] (free register pair)
    //   odd  j -> pack2 (CSE dedupes the A/B shared uses)
    #define UPAIR(j) (((j) & 1) ? pack2(in.f[j], in.f[(j) + 1]) : in.d[(j) / 2])

    // horizontal, split accumulator chains, consuming d[0] (first load) first
    #define HORIZ(hA, hB) do {                                       \
        u64 hA0 = 0ull, hA1 = 0ull, hB0 = 0ull, hB1 = 0ull;          \
        _Pragma("unroll")                                            \
        for (int j = 0; j < 15; ++j) {                               \
            const u64 uj = UPAIR(j);                                 \
            if (j <= 7) hA0 = fma2(HWM(j), uj, hA0);                 \
            else        hA1 = fma2(HWM(j), uj, hA1);                 \
        }                                                            \
        _Pragma("unroll")                                            \
        for (int j = 0; j < 15; ++j) {                               \
            const u64 uj = UPAIR(j + 2);                             \
            if (j <= 7) hB0 = fma2(HWM(j), uj, hB0);                 \
            else        hB1 = fma2(HWM(j), uj, hB1);                 \
        }                                                            \
        hA = add2(hA0, hA1);                                         \
        hB = add2(hB0, hB1);                                         \
    } while (0)

    // register ring of horizontal results: 15 rows x 2 packed pairs
    u64 rA[15], rB[15];
    #pragma unroll
    for (int i = 0; i < 14; ++i) {
        LOAD_ROW();                        // rows y0..y0+13 <= 461, always valid
        HORIZ(rA[i], rB[i]);
        p += W;
    }

    u64 fA = 0ull, fB = 0ull;

    // skewed loop: iteration i loads/filters input row y0+14+i and computes
    // vertical output row y0+i-1 (valid for i in [1, TILE]).
    for (int g = 0; g < 4; ++g) {
        #pragma unroll
        for (int q = 0; q < 15; ++q) {
            const int i = g * 15 + q;
            const bool doLoad = (i < TILE) && (y0 + 14 + i < W);
            const bool doVert = (i >= 1) && (i <= TILE) && (y0 + i - 1 < OUTW);

            // (1) loads for input row y0+14+i (skip => stale data, which only
            //     feeds discarded outputs >= 498)
            if (doLoad) LOAD_ROW();
            p += W;

            // (2) vertical for output row y0+i-1 (register-only; covers LDG)
            if (doVert) {
                u64 aA = 0ull, bA = 0ull, aB = 0ull, bB = 0ull;
                #pragma unroll
                for (int k = 0; k < 7; ++k) {
                    aA = fma2(vp[k], rA[(q - 1 + k + 15) % 15], aA);
                    bA = fma2(vp[k], rA[(q + 13 - k + 15) % 15], bA);
                    aB = fma2(vp[k], rB[(q - 1 + k + 15) % 15], aB);
                    bB = fma2(vp[k], rB[(q + 13 - k + 15) % 15], bB);
                }
                u64 oA = add2(aA, neg2(bA));
                u64 oB = add2(aB, neg2(bB));
                if (t >= 124) { oA &= mA; oB &= mB; }   // edge warp only
                fA = fma2(oA, oA, fA);
                fB = fma2(oB, oB, fB);
            }

            // (3) horizontal of the loaded row, insert into ring slot
            if (doLoad) {
                HORIZ(rA[(14 + q) % 15], rB[(14 + q) % 15]);
            }
        }
    }

    // deterministic block reduction in double
    {
        const u64 facc = add2(fA, fB);
        float flo, fhi;
        unpack2(facc, flo, fhi);
        red[t] = (double)flo + (double)fhi;
    }
    __syncthreads();
    #pragma unroll
    for (int s = 64; s > 0; s >>= 1) {
        if (t < s) red[t] += red[t + s];
        __syncthreads();
    }
    if (t == 0) {
        g_partials[batch * TILES_Y + tileY] = red[0];
        __threadfence();
        const int old = atomicAdd(&g_count[batch], 1);
        if (old == TILES_Y - 1) {   // last block for this batch: fixed-order sum
            __threadfence();
            double s = 0.0;
            #pragma unroll
            for (int i = 0; i < TILES_Y; ++i)
                s += __ldcg(&g_partials[batch * TILES_Y + i]);
            out[batch] = (float)(s * (1.0 / ((double)OUTW * (double)OUTW)));
            g_count[batch] = 0;     // reset for next graph replay
        }
    }
}

// ---------------------------------------------------------------------------
// Host side: replicate numpy float64 semantics exactly (validated R1-R10).
// ---------------------------------------------------------------------------

// numpy's pairwise_sum for contiguous float64 (PW_BLOCKSIZE = 128)
static double np_pairwise(const double* a, int n)
{
    if (n < 8) {
        double res = 0.0;
        for (int i = 0; i < n; ++i) res += a[i];
        return res;
    }
    else if (n <= 128) {
        double r[8];
        for (int j = 0; j < 8; ++j) r[j] = a[j];
        int i;
        for (i = 8; i < n - (n % 8); i += 8)
            for (int j = 0; j < 8; ++j) r[j] += a[i + j];
        double res = ((r[0] + r[1]) + (r[2] + r[3])) + ((r[4] + r[5]) + (r[6] + r[7]));
        for (; i < n; ++i) res += a[i];
        return res;
    }
    else {
        int n2 = n / 2;
        n2 -= n2 % 8;
        return np_pairwise(a, n2) + np_pairwise(a + n2, n - n2);
    }
}

extern "C" void kernel_launch(void* const* d_in, const int* in_sizes, int n_in,
                              void* d_out, int out_size)
{
    (void)in_sizes; (void)n_in; (void)out_size;
    const float* x  = (const float*)d_in[0];
    float*      out = (float*)d_out;

    const double sig     = 7.0 / 2.5;              // N=15//2=7; sig = N/2.5
    const double sig2    = pow(sig, 2.0);          // sig ** 2 (CPython float_pow -> libm pow)
    const double twosig2 = 2.0 * sig2;
    const double denomG  = (2.0 * M_PI) * sig;

    double Gy[225];
    for (int i = 0; i < 15; ++i) {
        const int yy = i - 7;
        for (int j = 0; j < 15; ++j) {
            const int xx = j - 7;
            const double G = exp((double)(-(xx * xx + yy * yy)) / twosig2) / denomG;
            Gy[i * 15 + j] = ((double)(-yy) * G) / sig2;
        }
    }
    const double s = np_pairwise(Gy, 225);         // np.sum(Gy), numpy pairwise order

    Weights wt;
    for (int j = 0; j < 8; ++j) {
        const int xx = j - 7;
        wt.hw[j] = (float)(exp((double)(-(xx * xx)) / twosig2) / denomG);
    }
    for (int k = 0; k < 7; ++k) {
        const int yy = k - 7;
        const double A = (((double)(-yy) * exp((double)(-(yy * yy)) / twosig2)) / sig2) / s;
        wt.vw[k] = (float)A;
    }

    dim3 grid(TILES_Y, NB);
    gder_kernel<<<grid, 128>>>(x, wt, out);
}